// round 1
// baseline (speedup 1.0000x reference)
#include <cuda_runtime.h>
#include <math.h>

#define NMAX 1024
#define CHUNK 256
#define L2E 1.4426950408889634f
#define TTHR 1.0e-4f
#define ECUT -26.6f   // log2(w) cutoff: w < 2^-26.6 ~ 1e-8 -> negligible, (1-w) rounds to 1.0f

// Unsorted per-gaussian params
__device__ float g_umx[NMAX], g_umy[NMAX], g_ucut2[NMAX];
__device__ float4 g_ugp[NMAX * 3];
__device__ unsigned long long g_key[NMAX];
// Sorted (by depth) params
__device__ float g_smx[NMAX], g_smy[NMAX], g_scut2[NMAX];
__device__ float4 g_sgp[NMAX * 3];

// ---------------------------------------------------------------------------
// Kernel 1: per-gaussian precompute
// ---------------------------------------------------------------------------
__global__ void precompute_kernel(const float* __restrict__ mean,
                                  const float* __restrict__ qvec,
                                  const float* __restrict__ svecb,
                                  const float* __restrict__ sh,
                                  const float* __restrict__ alphab,
                                  const float* __restrict__ c2w,
                                  int N)
{
    int n = blockIdx.x * blockDim.x + threadIdx.x;
    if (n >= N) return;

    float cw[16];
#pragma unroll
    for (int i = 0; i < 16; i++) cw[i] = __ldg(c2w + i);

    // p = Rw @ (mean - t), Rw = c2w[:3,:3]^T, t = c2w[:3,3]
    float d0 = mean[3 * n + 0] - cw[3];
    float d1 = mean[3 * n + 1] - cw[7];
    float d2 = mean[3 * n + 2] - cw[11];
    // p_i = sum_j c2w[j*4+i] * d_j   (Rw[i][j] = c2w[j][i])
    float px = cw[0] * d0 + cw[4] * d1 + cw[8]  * d2;
    float py = cw[1] * d0 + cw[5] * d1 + cw[9]  * d2;
    float pz = cw[2] * d0 + cw[6] * d1 + cw[10] * d2;

    float z = fmaxf(pz, 0.001f);
    // stable sort key: (z_bits, index) — z > 0 so float bits are monotone
    g_key[n] = ((unsigned long long)__float_as_uint(z) << 32) | (unsigned)n;

    float mx = px / z;
    float my = py / z;

    // quaternion -> rotation (normalized)
    float qw = qvec[4 * n + 0], qx = qvec[4 * n + 1], qy = qvec[4 * n + 2], qz = qvec[4 * n + 3];
    float qn = rsqrtf(qw * qw + qx * qx + qy * qy + qz * qz);
    qw *= qn; qx *= qn; qy *= qn; qz *= qn;
    float R00 = 1.f - 2.f * (qy * qy + qz * qz);
    float R01 = 2.f * (qx * qy - qw * qz);
    float R02 = 2.f * (qx * qz + qw * qy);
    float R10 = 2.f * (qx * qy + qw * qz);
    float R11 = 1.f - 2.f * (qx * qx + qz * qz);
    float R12 = 2.f * (qy * qz - qw * qx);
    float R20 = 2.f * (qx * qz - qw * qy);
    float R21 = 2.f * (qy * qz + qw * qx);
    float R22 = 1.f - 2.f * (qx * qx + qy * qy);

    float s0 = expf(svecb[3 * n + 0]);
    float s1 = expf(svecb[3 * n + 1]);
    float s2 = expf(svecb[3 * n + 2]);

    // M = Rq * diag(s); cov3d = M M^T (symmetric)
    float M00 = R00 * s0, M01 = R01 * s1, M02 = R02 * s2;
    float M10 = R10 * s0, M11 = R11 * s1, M12 = R12 * s2;
    float M20 = R20 * s0, M21 = R21 * s1, M22 = R22 * s2;
    float v00 = M00 * M00 + M01 * M01 + M02 * M02;
    float v01 = M00 * M10 + M01 * M11 + M02 * M12;
    float v02 = M00 * M20 + M01 * M21 + M02 * M22;
    float v11 = M10 * M10 + M11 * M11 + M12 * M12;
    float v12 = M10 * M20 + M11 * M21 + M12 * M22;
    float v22 = M20 * M20 + M21 * M21 + M22 * M22;

    // Rw rows: Rw[i][j] = c2w[j*4+i]
    float W00 = cw[0], W01 = cw[4], W02 = cw[8];
    float W10 = cw[1], W11 = cw[5], W12 = cw[9];
    float W20 = cw[2], W21 = cw[6], W22 = cw[10];

    // tmp = Rw * cov3d  (3x3)
    float t00 = W00 * v00 + W01 * v01 + W02 * v02;
    float t01 = W00 * v01 + W01 * v11 + W02 * v12;
    float t02 = W00 * v02 + W01 * v12 + W02 * v22;
    float t10 = W10 * v00 + W11 * v01 + W12 * v02;
    float t11 = W10 * v01 + W11 * v11 + W12 * v12;
    float t12 = W10 * v02 + W11 * v12 + W12 * v22;
    float t20 = W20 * v00 + W21 * v01 + W22 * v02;
    float t21 = W20 * v01 + W21 * v11 + W22 * v12;
    float t22 = W20 * v02 + W21 * v12 + W22 * v22;

    // cov_cam = tmp * Rw^T
    float c00 = t00 * W00 + t01 * W01 + t02 * W02;
    float c01 = t00 * W10 + t01 * W11 + t02 * W12;
    float c02 = t00 * W20 + t01 * W21 + t02 * W22;
    float c11 = t10 * W10 + t11 * W11 + t12 * W12;
    float c12 = t10 * W20 + t11 * W21 + t12 * W22;
    float c22 = t20 * W20 + t21 * W21 + t22 * W22;
    (void)c02;

    // J = [[iz,0,-x iz^2],[0,iz,-y iz^2]]; cov2d = J cov_cam J^T
    float iz = 1.f / z;
    float iz2 = iz * iz;
    float j02 = -px * iz2;
    float j12 = -py * iz2;
    // row0 of (J * cov_cam): [iz*c00 + j02*c02, iz*c01 + j02*c12, iz*c02 + j02*c22]
    float r0a = iz * c00 + j02 * c02;
    float r0b = iz * c01 + j02 * c12;
    float r0c = iz * c02 + j02 * c22;
    float r1a = iz * c01 + j12 * c02;
    float r1b = iz * c11 + j12 * c12;
    float r1c = iz * c12 + j12 * c22;
    float a2d = r0a * iz + r0c * j02 + 1e-8f;
    float b2d = r0b * iz + r0c * j12;
    float c2d = r1b * iz + r1c * j12 + 1e-8f;
    (void)r1a;

    float det = a2d * c2d - b2d * b2d;
    float ia = c2d / det;
    float ib = -b2d / det;
    float ic = a2d / det;

    // log2-domain exponent coefficients: log2(w) = A dx^2 + B dx dy + C dy^2 + la
    float A = -0.5f * L2E * ia;
    float B = -L2E * ib;
    float C = -0.5f * L2E * ic;

    float alpha = 1.f / (1.f + expf(-alphab[n]));
    float la = log2f(alpha);

    // conservative cull radius: quad >= lam_min(invcov) * dist^2
    float mid = 0.5f * (ia + ic);
    float dif = 0.5f * (ia - ic);
    float disc = sqrtf(fmaxf(dif * dif + ib * ib, 0.f));
    float lam = mid - disc;
    float cut2;
    if (la <= ECUT) cut2 = -1.f;                    // never contributes
    else cut2 = (la - ECUT) / (0.5f * L2E * fmaxf(lam, 1e-30f));

    const float SHB = 0.28209479177387814f;
    float cr = 1.f / (1.f + expf(-SHB * sh[n * 27 + 0]));
    float cg = 1.f / (1.f + expf(-SHB * sh[n * 27 + 9]));
    float cb = 1.f / (1.f + expf(-SHB * sh[n * 27 + 18]));

    g_umx[n] = mx; g_umy[n] = my; g_ucut2[n] = cut2;
    g_ugp[3 * n + 0] = make_float4(mx, my, A, B);
    g_ugp[3 * n + 1] = make_float4(C, la, cr, cg);
    g_ugp[3 * n + 2] = make_float4(cb, 0.f, 0.f, 0.f);
}

// ---------------------------------------------------------------------------
// Kernel 2: single-block bitonic sort of (z,index) keys + gather into sorted SoA
// ---------------------------------------------------------------------------
__global__ void __launch_bounds__(NMAX) sort_gather_kernel(int N)
{
    __shared__ unsigned long long sk[NMAX];
    int t = threadIdx.x;
    sk[t] = (t < N) ? g_key[t] : 0xFFFFFFFFFFFFFFFFull;
    __syncthreads();

    for (int k = 2; k <= NMAX; k <<= 1) {
        for (int j = k >> 1; j > 0; j >>= 1) {
            int ixj = t ^ j;
            if (ixj > t) {
                unsigned long long va = sk[t], vb = sk[ixj];
                bool up = ((t & k) == 0);
                if ((va > vb) == up) { sk[t] = vb; sk[ixj] = va; }
            }
            __syncthreads();
        }
    }

    if (t < N) {
        int o = (int)(sk[t] & 0xFFFFFFFFu);
        g_smx[t] = g_umx[o];
        g_smy[t] = g_umy[o];
        g_scut2[t] = g_ucut2[o];
        g_sgp[3 * t + 0] = g_ugp[3 * o + 0];
        g_sgp[3 * t + 1] = g_ugp[3 * o + 1];
        g_sgp[3 * t + 2] = g_ugp[3 * o + 2];
    }
}

// ---------------------------------------------------------------------------
// Kernel 3: tiled front-to-back compositing. One 16x16 pixel tile per block.
// ---------------------------------------------------------------------------
__global__ void __launch_bounds__(256) render_kernel(float* __restrict__ out,
                                                     int H, int W, int N)
{
    __shared__ float4 s_gp[CHUNK * 3];
    __shared__ int s_w[9];

    int tid = threadIdx.x;
    int lane = tid & 31;
    int wid = tid >> 5;
    int tx = tid & 15;
    int ty = tid >> 4;
    int pxi = blockIdx.x * 16 + tx;
    int pyi = blockIdx.y * 16 + ty;

    float invW = 1.f / (float)W;              // fx = fy = W, cx = W/2, cy = H/2
    float pxc = ((float)pxi + 0.5f - 0.5f * (float)W) * invW;
    float pyc = ((float)pyi + 0.5f - 0.5f * (float)H) * invW;
    float xmin = ((float)(blockIdx.x * 16)      + 0.5f - 0.5f * (float)W) * invW;
    float xmax = ((float)(blockIdx.x * 16 + 15) + 0.5f - 0.5f * (float)W) * invW;
    float ymin = ((float)(blockIdx.y * 16)      + 0.5f - 0.5f * (float)H) * invW;
    float ymax = ((float)(blockIdx.y * 16 + 15) + 0.5f - 0.5f * (float)H) * invW;

    float T = 1.f, ar = 0.f, ag = 0.f, ab = 0.f;

    for (int cs = 0; cs < N; cs += CHUNK) {
        // ---- cull: one gaussian per thread ----
        int i = cs + tid;
        int ok = 0;
        if (i < N) {
            float mx = g_smx[i], my = g_smy[i], c2 = g_scut2[i];
            float ddx = fmaxf(fmaxf(xmin - mx, mx - xmax), 0.f);
            float ddy = fmaxf(fmaxf(ymin - my, my - ymax), 0.f);
            ok = (ddx * ddx + ddy * ddy) <= c2;
        }
        // ---- order-preserving compaction (ballot + popc + tiny cross-warp scan)
        unsigned m = __ballot_sync(0xFFFFFFFFu, ok);
        int wpre = __popc(m & ((1u << lane) - 1u));
        if (lane == 0) s_w[wid] = __popc(m);
        __syncthreads();
        if (tid == 0) {
            int s = 0;
#pragma unroll
            for (int w = 0; w < 8; w++) { int v = s_w[w]; s_w[w] = s; s += v; }
            s_w[8] = s;
        }
        __syncthreads();
        int total = s_w[8];
        if (ok) {
            int base = s_w[wid] + wpre;
            s_gp[base * 3 + 0] = g_sgp[i * 3 + 0];
            s_gp[base * 3 + 1] = g_sgp[i * 3 + 1];
            s_gp[base * 3 + 2] = g_sgp[i * 3 + 2];
        }
        __syncthreads();

        // ---- composite survivors, in z order ----
        if (T > TTHR) {
            for (int k = 0; k < total; k++) {
                float4 p0 = s_gp[3 * k + 0];
                float4 p1 = s_gp[3 * k + 1];
                float dx = pxc - p0.x;
                float dy = pyc - p0.y;
                float e = fmaf(p0.z * dx, dx, fmaf(p0.w * dx, dy, p1.x * dy * dy)) + p1.y;
                if (e > ECUT) {
                    float w;
                    asm("ex2.approx.ftz.f32 %0, %1;" : "=f"(w) : "f"(e));
                    float wT = w * T;
                    float cb = s_gp[3 * k + 2].x;
                    ar = fmaf(wT, p1.z, ar);
                    ag = fmaf(wT, p1.w, ag);
                    ab = fmaf(wT, cb, ab);
                    T *= 1.f - fminf(w, 0.9999f);
                    if (T <= TTHR) break;
                }
            }
        }
        // uniform block-wide early exit + barrier protecting smem reuse
        if (__syncthreads_and(T <= TTHR)) break;
    }

    if (pxi < W && pyi < H) {
        int o = (pyi * W + pxi) * 3;
        out[o + 0] = ar;
        out[o + 1] = ag;
        out[o + 2] = ab;
    }
}

// ---------------------------------------------------------------------------
extern "C" void kernel_launch(void* const* d_in, const int* in_sizes, int n_in,
                              void* d_out, int out_size)
{
    const float* mean  = (const float*)d_in[0];
    const float* qvec  = (const float*)d_in[1];
    const float* svecb = (const float*)d_in[2];
    const float* sh    = (const float*)d_in[3];
    const float* alphb = (const float*)d_in[4];
    const float* c2w   = (const float*)d_in[5];

    int N = in_sizes[0] / 3;
    if (N > NMAX) N = NMAX;
    int HW = out_size / 3;
    int W = (int)(sqrtf((float)HW) + 0.5f);   // square image (256x256)
    int H = HW / W;

    precompute_kernel<<<(N + 255) / 256, 256>>>(mean, qvec, svecb, sh, alphb, c2w, N);
    sort_gather_kernel<<<1, NMAX>>>(N);
    dim3 grid((W + 15) / 16, (H + 15) / 16);
    render_kernel<<<grid, 256>>>((float*)d_out, H, W, N);
}

// round 2
// speedup vs baseline: 1.1659x; 1.1659x over previous
#include <cuda_runtime.h>
#include <math.h>

#define NMAX 1024
#define L2E 1.4426950408889634f
#define TTHR 1.0e-4f
#define ECUT -26.6f   // log2(w) cutoff: w < 2^-26.6 ~ 1e-8 -> negligible

// Unsorted per-gaussian params (scratch)
__device__ float4 g_u0[NMAX];          // mx, my, A, B
__device__ float4 g_u1[NMAX];          // C, la, cr, cg
__device__ float2 g_u2[NMAX];          // cb, cut2
// Sorted (by depth) params
__device__ float4 g_s0[NMAX];
__device__ float4 g_s1[NMAX];
__device__ float2 g_s2[NMAX];

// ---------------------------------------------------------------------------
// Kernel 1: fused per-gaussian precompute + single-block bitonic sort + gather
// ---------------------------------------------------------------------------
__global__ void __launch_bounds__(NMAX) precompute_sort_kernel(
    const float* __restrict__ mean,
    const float* __restrict__ qvec,
    const float* __restrict__ svecb,
    const float* __restrict__ sh,
    const float* __restrict__ alphab,
    const float* __restrict__ c2w,
    int N)
{
    __shared__ unsigned long long kbuf[2][NMAX];   // 16KB double buffer

    int t = threadIdx.x;
    unsigned long long key = 0xFFFFFFFFFFFFFFFFull;

    if (t < N) {
        float cw[16];
#pragma unroll
        for (int i = 0; i < 16; i++) cw[i] = __ldg(c2w + i);

        int n = t;
        float d0 = mean[3 * n + 0] - cw[3];
        float d1 = mean[3 * n + 1] - cw[7];
        float d2 = mean[3 * n + 2] - cw[11];
        float px = cw[0] * d0 + cw[4] * d1 + cw[8]  * d2;
        float py = cw[1] * d0 + cw[5] * d1 + cw[9]  * d2;
        float pz = cw[2] * d0 + cw[6] * d1 + cw[10] * d2;

        float z = fmaxf(pz, 0.001f);
        key = ((unsigned long long)__float_as_uint(z) << 32) | (unsigned)n;

        float mx = px / z;
        float my = py / z;

        float qw = qvec[4 * n + 0], qx = qvec[4 * n + 1], qy = qvec[4 * n + 2], qz = qvec[4 * n + 3];
        float qn = rsqrtf(qw * qw + qx * qx + qy * qy + qz * qz);
        qw *= qn; qx *= qn; qy *= qn; qz *= qn;
        float R00 = 1.f - 2.f * (qy * qy + qz * qz);
        float R01 = 2.f * (qx * qy - qw * qz);
        float R02 = 2.f * (qx * qz + qw * qy);
        float R10 = 2.f * (qx * qy + qw * qz);
        float R11 = 1.f - 2.f * (qx * qx + qz * qz);
        float R12 = 2.f * (qy * qz - qw * qx);
        float R20 = 2.f * (qx * qz - qw * qy);
        float R21 = 2.f * (qy * qz + qw * qx);
        float R22 = 1.f - 2.f * (qx * qx + qy * qy);

        float s0 = expf(svecb[3 * n + 0]);
        float s1 = expf(svecb[3 * n + 1]);
        float s2 = expf(svecb[3 * n + 2]);

        float M00 = R00 * s0, M01 = R01 * s1, M02 = R02 * s2;
        float M10 = R10 * s0, M11 = R11 * s1, M12 = R12 * s2;
        float M20 = R20 * s0, M21 = R21 * s1, M22 = R22 * s2;
        float v00 = M00 * M00 + M01 * M01 + M02 * M02;
        float v01 = M00 * M10 + M01 * M11 + M02 * M12;
        float v02 = M00 * M20 + M01 * M21 + M02 * M22;
        float v11 = M10 * M10 + M11 * M11 + M12 * M12;
        float v12 = M10 * M20 + M11 * M21 + M12 * M22;
        float v22 = M20 * M20 + M21 * M21 + M22 * M22;

        float W00 = cw[0], W01 = cw[4], W02 = cw[8];
        float W10 = cw[1], W11 = cw[5], W12 = cw[9];
        float W20 = cw[2], W21 = cw[6], W22 = cw[10];

        float t00 = W00 * v00 + W01 * v01 + W02 * v02;
        float t01 = W00 * v01 + W01 * v11 + W02 * v12;
        float t02 = W00 * v02 + W01 * v12 + W02 * v22;
        float t10 = W10 * v00 + W11 * v01 + W12 * v02;
        float t11 = W10 * v01 + W11 * v11 + W12 * v12;
        float t12 = W10 * v02 + W11 * v12 + W12 * v22;
        float t20 = W20 * v00 + W21 * v01 + W22 * v02;
        float t21 = W20 * v01 + W21 * v11 + W22 * v12;
        float t22 = W20 * v02 + W21 * v12 + W22 * v22;

        float c00 = t00 * W00 + t01 * W01 + t02 * W02;
        float c01 = t00 * W10 + t01 * W11 + t02 * W12;
        float c02 = t00 * W20 + t01 * W21 + t02 * W22;
        float c11 = t10 * W10 + t11 * W11 + t12 * W12;
        float c12 = t10 * W20 + t11 * W21 + t12 * W22;
        float c22 = t20 * W20 + t21 * W21 + t22 * W22;
        (void)t21;

        float iz = 1.f / z;
        float iz2 = iz * iz;
        float j02 = -px * iz2;
        float j12 = -py * iz2;
        float r0a = iz * c00 + j02 * c02;
        float r0b = iz * c01 + j02 * c12;
        float r0c = iz * c02 + j02 * c22;
        float r1b = iz * c11 + j12 * c12;
        float r1c = iz * c12 + j12 * c22;
        float a2d = r0a * iz + r0c * j02 + 1e-8f;
        float b2d = r0b * iz + r0c * j12;
        float c2d = r1b * iz + r1c * j12 + 1e-8f;

        float det = a2d * c2d - b2d * b2d;
        float ia = c2d / det;
        float ib = -b2d / det;
        float ic = a2d / det;

        float A = -0.5f * L2E * ia;
        float B = -L2E * ib;
        float C = -0.5f * L2E * ic;

        float alpha = 1.f / (1.f + expf(-alphab[n]));
        float la = log2f(alpha);

        float mid = 0.5f * (ia + ic);
        float dif = 0.5f * (ia - ic);
        float disc = sqrtf(fmaxf(dif * dif + ib * ib, 0.f));
        float lam = mid - disc;
        float cut2 = (la <= ECUT) ? -1.f
                                  : (la - ECUT) / (0.5f * L2E * fmaxf(lam, 1e-30f));

        const float SHB = 0.28209479177387814f;
        float cr = 1.f / (1.f + expf(-SHB * sh[n * 27 + 0]));
        float cg = 1.f / (1.f + expf(-SHB * sh[n * 27 + 9]));
        float cb = 1.f / (1.f + expf(-SHB * sh[n * 27 + 18]));

        g_u0[n] = make_float4(mx, my, A, B);
        g_u1[n] = make_float4(C, la, cr, cg);
        g_u2[n] = make_float2(cb, cut2);
    }

    __syncthreads();   // params visible to block; keys ready

    // ---- hybrid bitonic sort: shfl for j<32, double-buffered smem for j>=32
    int cur = 0;
#pragma unroll
    for (int k = 2; k <= NMAX; k <<= 1) {
        for (int j = k >> 1; j > 0; j >>= 1) {
            bool takeMin = (((t & j) == 0) == ((t & k) == 0));
            unsigned long long o;
            if (j < 32) {
                o = __shfl_xor_sync(0xFFFFFFFFu, key, j);
            } else {
                kbuf[cur][t] = key;
                __syncthreads();
                o = kbuf[cur][t ^ j];
                cur ^= 1;
            }
            key = takeMin ? (key < o ? key : o) : (key < o ? o : key);
        }
    }
    __syncthreads();

    if (t < N) {
        int o = (int)(key & 0xFFFFFFFFu);
        g_s0[t] = g_u0[o];
        g_s1[t] = g_u1[o];
        g_s2[t] = g_u2[o];
    }
}

// ---------------------------------------------------------------------------
// Kernel 2: tiled front-to-back compositing. One 16x16 pixel tile per block.
// Single cull pass over all N, one scan, barrier-free composite loop.
// ---------------------------------------------------------------------------
__global__ void __launch_bounds__(256) render_kernel(float* __restrict__ out,
                                                     int H, int W, int N)
{
    __shared__ float4 s0[NMAX];   // 16KB
    __shared__ float4 s1[NMAX];   // 16KB
    __shared__ float  s2[NMAX];   // 4KB
    __shared__ int    s_w[9];

    int tid = threadIdx.x;
    int lane = tid & 31;
    int wid = tid >> 5;
    int tx = tid & 15;
    int ty = tid >> 4;
    int pxi = blockIdx.x * 16 + tx;
    int pyi = blockIdx.y * 16 + ty;

    float invW = 1.f / (float)W;
    float pxc = ((float)pxi + 0.5f - 0.5f * (float)W) * invW;
    float pyc = ((float)pyi + 0.5f - 0.5f * (float)H) * invW;
    float xmin = ((float)(blockIdx.x * 16)      + 0.5f - 0.5f * (float)W) * invW;
    float xmax = ((float)(blockIdx.x * 16 + 15) + 0.5f - 0.5f * (float)W) * invW;
    float ymin = ((float)(blockIdx.y * 16)      + 0.5f - 0.5f * (float)H) * invW;
    float ymax = ((float)(blockIdx.y * 16 + 15) + 0.5f - 0.5f * (float)H) * invW;

    // ---- cull all N gaussians: 4 contiguous per thread (order preserved) ----
    float4 p0s[4];
    float  cbs[4];
    int flags = 0, cnt = 0;
#pragma unroll
    for (int r = 0; r < 4; r++) {
        int i = tid * 4 + r;
        if (i < N) {
            float4 p0 = g_s0[i];
            float2 p2 = g_s2[i];
            float ddx = fmaxf(fmaxf(xmin - p0.x, p0.x - xmax), 0.f);
            float ddy = fmaxf(fmaxf(ymin - p0.y, p0.y - ymax), 0.f);
            if (ddx * ddx + ddy * ddy <= p2.y) {
                p0s[cnt & 3] = p0;
                cbs[cnt & 3] = p2.x;
                flags |= 1 << r;
                cnt++;
            }
        }
    }

    // ---- block exclusive scan of per-thread counts ----
    int incl = cnt;
#pragma unroll
    for (int d = 1; d < 32; d <<= 1) {
        int v = __shfl_up_sync(0xFFFFFFFFu, incl, d);
        if (lane >= d) incl += v;
    }
    if (lane == 31) s_w[wid] = incl;
    __syncthreads();
    if (tid == 0) {
        int s = 0;
#pragma unroll
        for (int w = 0; w < 8; w++) { int v = s_w[w]; s_w[w] = s; s += v; }
        s_w[8] = s;
    }
    __syncthreads();
    int base = s_w[wid] + incl - cnt;
    int total = s_w[8];

    // ---- write survivors to smem (p0 from regs; p1 loaded now) ----
    {
        int c = 0;
#pragma unroll
        for (int r = 0; r < 4; r++) {
            if (flags & (1 << r)) {
                int i = tid * 4 + r;
                s0[base + c] = p0s[c & 3];
                s1[base + c] = g_s1[i];
                s2[base + c] = cbs[c & 3];
                c++;
            }
        }
    }
    __syncthreads();

    // ---- composite survivors in z order, per-pixel early exit ----
    float T = 1.f, ar = 0.f, ag = 0.f, ab = 0.f;
    for (int k = 0; k < total; k++) {
        float4 p0 = s0[k];
        float4 p1 = s1[k];
        float dx = pxc - p0.x;
        float dy = pyc - p0.y;
        float e = fmaf(p0.z * dx, dx, fmaf(p0.w * dx, dy, p1.x * dy * dy)) + p1.y;
        if (e > ECUT) {
            float w;
            asm("ex2.approx.ftz.f32 %0, %1;" : "=f"(w) : "f"(e));
            float wT = w * T;
            float cb = s2[k];
            ar = fmaf(wT, p1.z, ar);
            ag = fmaf(wT, p1.w, ag);
            ab = fmaf(wT, cb, ab);
            T *= 1.f - fminf(w, 0.9999f);
            if (T <= TTHR) break;
        }
    }

    if (pxi < W && pyi < H) {
        int o = (pyi * W + pxi) * 3;
        out[o + 0] = ar;
        out[o + 1] = ag;
        out[o + 2] = ab;
    }
}

// ---------------------------------------------------------------------------
extern "C" void kernel_launch(void* const* d_in, const int* in_sizes, int n_in,
                              void* d_out, int out_size)
{
    const float* mean  = (const float*)d_in[0];
    const float* qvec  = (const float*)d_in[1];
    const float* svecb = (const float*)d_in[2];
    const float* sh    = (const float*)d_in[3];
    const float* alphb = (const float*)d_in[4];
    const float* c2w   = (const float*)d_in[5];

    int N = in_sizes[0] / 3;
    if (N > NMAX) N = NMAX;
    int HW = out_size / 3;
    int W = (int)(sqrtf((float)HW) + 0.5f);
    int H = HW / W;

    precompute_sort_kernel<<<1, NMAX>>>(mean, qvec, svecb, sh, alphb, c2w, N);
    dim3 grid((W + 15) / 16, (H + 15) / 16);
    render_kernel<<<grid, 256>>>((float*)d_out, H, W, N);
}

// round 3
// speedup vs baseline: 1.7178x; 1.4733x over previous
#include <cuda_runtime.h>
#include <math.h>

#define NMAX 1024
#define L2E 1.4426950408889634f
#define TTHR 1.0e-4f
#define ECUT -26.6f

typedef unsigned long long ull;

// Per-gaussian params (unsorted, indexed by original gaussian id)
__device__ float4 g_cull[NMAX];   // mx, my, cut2, z_bits(as float)
__device__ float4 g_p0[NMAX];     // mx, my, A, B
__device__ float4 g_p1[NMAX];     // C, la, cr, cg
__device__ float  g_cb[NMAX];     // blue

// ---------------------------------------------------------------------------
// Kernel 1: per-gaussian precompute (parallel grid)
// ---------------------------------------------------------------------------
__global__ void precompute_kernel(const float* __restrict__ mean,
                                  const float* __restrict__ qvec,
                                  const float* __restrict__ svecb,
                                  const float* __restrict__ sh,
                                  const float* __restrict__ alphab,
                                  const float* __restrict__ c2w,
                                  int N)
{
    int n = blockIdx.x * blockDim.x + threadIdx.x;
    if (n >= N) return;

    float cw[16];
#pragma unroll
    for (int i = 0; i < 16; i++) cw[i] = __ldg(c2w + i);

    float d0 = mean[3 * n + 0] - cw[3];
    float d1 = mean[3 * n + 1] - cw[7];
    float d2 = mean[3 * n + 2] - cw[11];
    float px = cw[0] * d0 + cw[4] * d1 + cw[8]  * d2;
    float py = cw[1] * d0 + cw[5] * d1 + cw[9]  * d2;
    float pz = cw[2] * d0 + cw[6] * d1 + cw[10] * d2;

    float z = fmaxf(pz, 0.001f);
    float mx = px / z;
    float my = py / z;

    float qw = qvec[4 * n + 0], qx = qvec[4 * n + 1], qy = qvec[4 * n + 2], qz = qvec[4 * n + 3];
    float qn = rsqrtf(qw * qw + qx * qx + qy * qy + qz * qz);
    qw *= qn; qx *= qn; qy *= qn; qz *= qn;
    float R00 = 1.f - 2.f * (qy * qy + qz * qz);
    float R01 = 2.f * (qx * qy - qw * qz);
    float R02 = 2.f * (qx * qz + qw * qy);
    float R10 = 2.f * (qx * qy + qw * qz);
    float R11 = 1.f - 2.f * (qx * qx + qz * qz);
    float R12 = 2.f * (qy * qz - qw * qx);
    float R20 = 2.f * (qx * qz - qw * qy);
    float R21 = 2.f * (qy * qz + qw * qx);
    float R22 = 1.f - 2.f * (qx * qx + qy * qy);

    float s0 = expf(svecb[3 * n + 0]);
    float s1 = expf(svecb[3 * n + 1]);
    float s2 = expf(svecb[3 * n + 2]);

    float M00 = R00 * s0, M01 = R01 * s1, M02 = R02 * s2;
    float M10 = R10 * s0, M11 = R11 * s1, M12 = R12 * s2;
    float M20 = R20 * s0, M21 = R21 * s1, M22 = R22 * s2;
    float v00 = M00 * M00 + M01 * M01 + M02 * M02;
    float v01 = M00 * M10 + M01 * M11 + M02 * M12;
    float v02 = M00 * M20 + M01 * M21 + M02 * M22;
    float v11 = M10 * M10 + M11 * M11 + M12 * M12;
    float v12 = M10 * M20 + M11 * M21 + M12 * M22;
    float v22 = M20 * M20 + M21 * M21 + M22 * M22;

    float W00 = cw[0], W01 = cw[4], W02 = cw[8];
    float W10 = cw[1], W11 = cw[5], W12 = cw[9];
    float W20 = cw[2], W21 = cw[6], W22 = cw[10];

    float t00 = W00 * v00 + W01 * v01 + W02 * v02;
    float t01 = W00 * v01 + W01 * v11 + W02 * v12;
    float t02 = W00 * v02 + W01 * v12 + W02 * v22;
    float t10 = W10 * v00 + W11 * v01 + W12 * v02;
    float t11 = W10 * v01 + W11 * v11 + W12 * v12;
    float t12 = W10 * v02 + W11 * v12 + W12 * v22;
    float t20 = W20 * v00 + W21 * v01 + W22 * v02;
    float t22 = W20 * v02 + W21 * v12 + W22 * v22;

    float c00 = t00 * W00 + t01 * W01 + t02 * W02;
    float c01 = t00 * W10 + t01 * W11 + t02 * W12;
    float c02 = t00 * W20 + t01 * W21 + t02 * W22;
    float c11 = t10 * W10 + t11 * W11 + t12 * W12;
    float c12 = t10 * W20 + t11 * W21 + t12 * W22;
    float c22 = t20 * W20 + t22 * W22 + t20 * 0.f;   // t21 unused; c22 = t20*W20 + t21*W21 + t22*W22
    // recompute c22 properly (t21 needed):
    {
        float t21 = W20 * v01 + W21 * v11 + W22 * v12;
        c22 = t20 * W20 + t21 * W21 + t22 * W22;
    }

    float iz = 1.f / z;
    float iz2 = iz * iz;
    float j02 = -px * iz2;
    float j12 = -py * iz2;
    float r0a = iz * c00 + j02 * c02;
    float r0b = iz * c01 + j02 * c12;
    float r0c = iz * c02 + j02 * c22;
    float r1b = iz * c11 + j12 * c12;
    float r1c = iz * c12 + j12 * c22;
    float a2d = r0a * iz + r0c * j02 + 1e-8f;
    float b2d = r0b * iz + r0c * j12;
    float c2d = r1b * iz + r1c * j12 + 1e-8f;

    float det = a2d * c2d - b2d * b2d;
    float ia = c2d / det;
    float ib = -b2d / det;
    float ic = a2d / det;

    float A = -0.5f * L2E * ia;
    float B = -L2E * ib;
    float C = -0.5f * L2E * ic;

    float alpha = 1.f / (1.f + expf(-alphab[n]));
    float la = log2f(alpha);

    float mid = 0.5f * (ia + ic);
    float dif = 0.5f * (ia - ic);
    float disc = sqrtf(fmaxf(dif * dif + ib * ib, 0.f));
    float lam = mid - disc;
    float cut2 = (la <= ECUT) ? -1.f
                              : (la - ECUT) / (0.5f * L2E * fmaxf(lam, 1e-30f));

    const float SHB = 0.28209479177387814f;
    float cr = 1.f / (1.f + expf(-SHB * sh[n * 27 + 0]));
    float cg = 1.f / (1.f + expf(-SHB * sh[n * 27 + 9]));
    float cb = 1.f / (1.f + expf(-SHB * sh[n * 27 + 18]));

    g_cull[n] = make_float4(mx, my, cut2, __uint_as_float(__float_as_uint(z)));
    g_p0[n]   = make_float4(mx, my, A, B);
    g_p1[n]   = make_float4(C, la, cr, cg);
    g_cb[n]   = cb;
}

// ---------------------------------------------------------------------------
// Kernel 2: per-tile cull -> tiny bitonic sort -> gather -> composite
// ---------------------------------------------------------------------------
__global__ void __launch_bounds__(256) render_kernel(float* __restrict__ out,
                                                     int H, int W, int N)
{
    __shared__ ull    skey[NMAX];   // 8KB
    __shared__ float4 f0[NMAX];     // 16KB
    __shared__ float4 f1[NMAX];     // 16KB
    __shared__ float  fcb[NMAX];    // 4KB
    __shared__ int    s_w[9];

    int tid = threadIdx.x;
    int lane = tid & 31;
    int wid = tid >> 5;
    int tx = tid & 15;
    int ty = tid >> 4;
    int pxi = blockIdx.x * 16 + tx;
    int pyi = blockIdx.y * 16 + ty;

    float invW = 1.f / (float)W;
    float pxc = ((float)pxi + 0.5f - 0.5f * (float)W) * invW;
    float pyc = ((float)pyi + 0.5f - 0.5f * (float)H) * invW;
    float xmin = ((float)(blockIdx.x * 16)      + 0.5f - 0.5f * (float)W) * invW;
    float xmax = ((float)(blockIdx.x * 16 + 15) + 0.5f - 0.5f * (float)W) * invW;
    float ymin = ((float)(blockIdx.y * 16)      + 0.5f - 0.5f * (float)H) * invW;
    float ymax = ((float)(blockIdx.y * 16 + 15) + 0.5f - 0.5f * (float)H) * invW;

    // ---- cull: 4 contiguous gaussians per thread, keys to registers ----
    ull lk[4];
    int cnt = 0;
#pragma unroll
    for (int r = 0; r < 4; r++) {
        int i = tid * 4 + r;
        if (i < N) {
            float4 c = g_cull[i];
            float ddx = fmaxf(fmaxf(xmin - c.x, c.x - xmax), 0.f);
            float ddy = fmaxf(fmaxf(ymin - c.y, c.y - ymax), 0.f);
            if (ddx * ddx + ddy * ddy <= c.z) {
                lk[cnt++] = ((ull)__float_as_uint(c.w) << 32) | (unsigned)i;
            }
        }
    }

    // ---- block exclusive scan of per-thread survivor counts ----
    int incl = cnt;
#pragma unroll
    for (int d = 1; d < 32; d <<= 1) {
        int v = __shfl_up_sync(0xFFFFFFFFu, incl, d);
        if (lane >= d) incl += v;
    }
    if (lane == 31) s_w[wid] = incl;
    __syncthreads();
    if (tid == 0) {
        int s = 0;
#pragma unroll
        for (int w = 0; w < 8; w++) { int v = s_w[w]; s_w[w] = s; s += v; }
        s_w[8] = s;
    }
    __syncthreads();
    int base = s_w[wid] + incl - cnt;
    int total = s_w[8];

    for (int j = 0; j < cnt; j++) skey[base + j] = lk[j];

    // ---- pad to power of two, bitonic sort keys ----
    int P = 1;
    while (P < total) P <<= 1;
    for (int i = total + tid; i < P; i += 256) skey[i] = 0xFFFFFFFFFFFFFFFFull;
    __syncthreads();

    for (int k = 2; k <= P; k <<= 1) {
        for (int j = k >> 1; j > 0; j >>= 1) {
            for (int i = tid; i < P; i += 256) {
                int ixj = i ^ j;
                if (ixj > i) {
                    ull a = skey[i], b = skey[ixj];
                    bool up = (i & k) == 0;
                    if ((a > b) == up) { skey[i] = b; skey[ixj] = a; }
                }
            }
            __syncthreads();
        }
    }

    // ---- gather params in sorted order ----
    for (int k = tid; k < total; k += 256) {
        int idx = (int)(skey[k] & 0xFFFFFFFFu);
        f0[k]  = g_p0[idx];
        f1[k]  = g_p1[idx];
        fcb[k] = g_cb[idx];
    }
    __syncthreads();

    // ---- composite, front to back, unrolled x2 ----
    float T = 1.f, ar = 0.f, ag = 0.f, ab = 0.f;
    int M = total;
    int Me = M & ~1;
    int k = 0;
    for (; k < Me; k += 2) {
        float4 p0a = f0[k],     p1a = f1[k];
        float4 p0b = f0[k + 1], p1b = f1[k + 1];
        float cba = fcb[k], cbb = fcb[k + 1];
        float dxa = pxc - p0a.x, dya = pyc - p0a.y;
        float dxb = pxc - p0b.x, dyb = pyc - p0b.y;
        float ea = fmaf(p0a.z * dxa, dxa, fmaf(p0a.w * dxa, dya, p1a.x * dya * dya)) + p1a.y;
        float eb = fmaf(p0b.z * dxb, dxb, fmaf(p0b.w * dxb, dyb, p1b.x * dyb * dyb)) + p1b.y;
        float wa, wb;
        asm("ex2.approx.ftz.f32 %0, %1;" : "=f"(wa) : "f"(ea));
        asm("ex2.approx.ftz.f32 %0, %1;" : "=f"(wb) : "f"(eb));
        float wTa = wa * T;
        ar = fmaf(wTa, p1a.z, ar);
        ag = fmaf(wTa, p1a.w, ag);
        ab = fmaf(wTa, cba, ab);
        float T1 = T * (1.f - fminf(wa, 0.9999f));
        if (T1 > TTHR) {
            float wTb = wb * T1;
            ar = fmaf(wTb, p1b.z, ar);
            ag = fmaf(wTb, p1b.w, ag);
            ab = fmaf(wTb, cbb, ab);
            T = T1 * (1.f - fminf(wb, 0.9999f));
            if (T <= TTHR) break;
        } else {
            T = T1;
            break;
        }
    }
    if (k == Me && Me < M && T > TTHR) {   // odd tail
        float4 p0a = f0[Me], p1a = f1[Me];
        float cba = fcb[Me];
        float dxa = pxc - p0a.x, dya = pyc - p0a.y;
        float ea = fmaf(p0a.z * dxa, dxa, fmaf(p0a.w * dxa, dya, p1a.x * dya * dya)) + p1a.y;
        float wa;
        asm("ex2.approx.ftz.f32 %0, %1;" : "=f"(wa) : "f"(ea));
        float wTa = wa * T;
        ar = fmaf(wTa, p1a.z, ar);
        ag = fmaf(wTa, p1a.w, ag);
        ab = fmaf(wTa, cba, ab);
    }

    if (pxi < W && pyi < H) {
        int o = (pyi * W + pxi) * 3;
        out[o + 0] = ar;
        out[o + 1] = ag;
        out[o + 2] = ab;
    }
}

// ---------------------------------------------------------------------------
extern "C" void kernel_launch(void* const* d_in, const int* in_sizes, int n_in,
                              void* d_out, int out_size)
{
    const float* mean  = (const float*)d_in[0];
    const float* qvec  = (const float*)d_in[1];
    const float* svecb = (const float*)d_in[2];
    const float* sh    = (const float*)d_in[3];
    const float* alphb = (const float*)d_in[4];
    const float* c2w   = (const float*)d_in[5];

    int N = in_sizes[0] / 3;
    if (N > NMAX) N = NMAX;
    int HW = out_size / 3;
    int W = (int)(sqrtf((float)HW) + 0.5f);
    int H = HW / W;

    precompute_kernel<<<(N + 255) / 256, 256>>>(mean, qvec, svecb, sh, alphb, c2w, N);
    dim3 grid((W + 15) / 16, (H + 15) / 16);
    render_kernel<<<grid, 256>>>((float*)d_out, H, W, N);
}

// round 4
// speedup vs baseline: 1.8946x; 1.1029x over previous
#include <cuda_runtime.h>
#include <math.h>

#define NMAX 1024
#define SMAX 256          // staged survivors per chunk
#define L2E 1.4426950408889634f
#define TTHR 1.0e-4f
#define ECUT -26.6f

typedef unsigned long long ull;

// Per-gaussian params (unsorted, indexed by original gaussian id)
__device__ float4 g_cull[NMAX];   // mx, my, cut2, z_bits(as float)
__device__ float4 g_p0[NMAX];     // mx, my, A, B
__device__ float4 g_p1[NMAX];     // C, la, cr, cg
__device__ float  g_cb[NMAX];     // blue

// ---------------------------------------------------------------------------
// Kernel 1: per-gaussian precompute (parallel grid)
// ---------------------------------------------------------------------------
__global__ void precompute_kernel(const float* __restrict__ mean,
                                  const float* __restrict__ qvec,
                                  const float* __restrict__ svecb,
                                  const float* __restrict__ sh,
                                  const float* __restrict__ alphab,
                                  const float* __restrict__ c2w,
                                  int N)
{
    int n = blockIdx.x * blockDim.x + threadIdx.x;
    if (n >= N) return;

    float cw[16];
#pragma unroll
    for (int i = 0; i < 16; i++) cw[i] = __ldg(c2w + i);

    float d0 = mean[3 * n + 0] - cw[3];
    float d1 = mean[3 * n + 1] - cw[7];
    float d2 = mean[3 * n + 2] - cw[11];
    float px = cw[0] * d0 + cw[4] * d1 + cw[8]  * d2;
    float py = cw[1] * d0 + cw[5] * d1 + cw[9]  * d2;
    float pz = cw[2] * d0 + cw[6] * d1 + cw[10] * d2;

    float z = fmaxf(pz, 0.001f);
    float mx = px / z;
    float my = py / z;

    float qw = qvec[4 * n + 0], qx = qvec[4 * n + 1], qy = qvec[4 * n + 2], qz = qvec[4 * n + 3];
    float qn = rsqrtf(qw * qw + qx * qx + qy * qy + qz * qz);
    qw *= qn; qx *= qn; qy *= qn; qz *= qn;
    float R00 = 1.f - 2.f * (qy * qy + qz * qz);
    float R01 = 2.f * (qx * qy - qw * qz);
    float R02 = 2.f * (qx * qz + qw * qy);
    float R10 = 2.f * (qx * qy + qw * qz);
    float R11 = 1.f - 2.f * (qx * qx + qz * qz);
    float R12 = 2.f * (qy * qz - qw * qx);
    float R20 = 2.f * (qx * qz - qw * qy);
    float R21 = 2.f * (qy * qz + qw * qx);
    float R22 = 1.f - 2.f * (qx * qx + qy * qy);

    float s0 = expf(svecb[3 * n + 0]);
    float s1 = expf(svecb[3 * n + 1]);
    float s2 = expf(svecb[3 * n + 2]);

    float M00 = R00 * s0, M01 = R01 * s1, M02 = R02 * s2;
    float M10 = R10 * s0, M11 = R11 * s1, M12 = R12 * s2;
    float M20 = R20 * s0, M21 = R21 * s1, M22 = R22 * s2;
    float v00 = M00 * M00 + M01 * M01 + M02 * M02;
    float v01 = M00 * M10 + M01 * M11 + M02 * M12;
    float v02 = M00 * M20 + M01 * M21 + M02 * M22;
    float v11 = M10 * M10 + M11 * M11 + M12 * M12;
    float v12 = M10 * M20 + M11 * M21 + M12 * M22;
    float v22 = M20 * M20 + M21 * M21 + M22 * M22;

    float W00 = cw[0], W01 = cw[4], W02 = cw[8];
    float W10 = cw[1], W11 = cw[5], W12 = cw[9];
    float W20 = cw[2], W21 = cw[6], W22 = cw[10];

    float t00 = W00 * v00 + W01 * v01 + W02 * v02;
    float t01 = W00 * v01 + W01 * v11 + W02 * v12;
    float t02 = W00 * v02 + W01 * v12 + W02 * v22;
    float t10 = W10 * v00 + W11 * v01 + W12 * v02;
    float t11 = W10 * v01 + W11 * v11 + W12 * v12;
    float t12 = W10 * v02 + W11 * v12 + W12 * v22;
    float t20 = W20 * v00 + W21 * v01 + W22 * v02;
    float t21 = W20 * v01 + W21 * v11 + W22 * v12;
    float t22 = W20 * v02 + W21 * v12 + W22 * v22;

    float c00 = t00 * W00 + t01 * W01 + t02 * W02;
    float c01 = t00 * W10 + t01 * W11 + t02 * W12;
    float c02 = t00 * W20 + t01 * W21 + t02 * W22;
    float c11 = t10 * W10 + t11 * W11 + t12 * W12;
    float c12 = t10 * W20 + t11 * W21 + t12 * W22;
    float c22 = t20 * W20 + t21 * W21 + t22 * W22;

    float iz = 1.f / z;
    float iz2 = iz * iz;
    float j02 = -px * iz2;
    float j12 = -py * iz2;
    float r0a = iz * c00 + j02 * c02;
    float r0b = iz * c01 + j02 * c12;
    float r0c = iz * c02 + j02 * c22;
    float r1b = iz * c11 + j12 * c12;
    float r1c = iz * c12 + j12 * c22;
    float a2d = r0a * iz + r0c * j02 + 1e-8f;
    float b2d = r0b * iz + r0c * j12;
    float c2d = r1b * iz + r1c * j12 + 1e-8f;

    float det = a2d * c2d - b2d * b2d;
    float ia = c2d / det;
    float ib = -b2d / det;
    float ic = a2d / det;

    float A = -0.5f * L2E * ia;
    float B = -L2E * ib;
    float C = -0.5f * L2E * ic;

    float alpha = 1.f / (1.f + expf(-alphab[n]));
    float la = log2f(alpha);

    float mid = 0.5f * (ia + ic);
    float dif = 0.5f * (ia - ic);
    float disc = sqrtf(fmaxf(dif * dif + ib * ib, 0.f));
    float lam = mid - disc;
    float cut2 = (la <= ECUT) ? -1.f
                              : (la - ECUT) / (0.5f * L2E * fmaxf(lam, 1e-30f));

    const float SHB = 0.28209479177387814f;
    float cr = 1.f / (1.f + expf(-SHB * sh[n * 27 + 0]));
    float cg = 1.f / (1.f + expf(-SHB * sh[n * 27 + 9]));
    float cb = 1.f / (1.f + expf(-SHB * sh[n * 27 + 18]));

    g_cull[n] = make_float4(mx, my, cut2, __uint_as_float(__float_as_uint(z)));
    g_p0[n]   = make_float4(mx, my, A, B);
    g_p1[n]   = make_float4(C, la, cr, cg);
    g_cb[n]   = cb;
}

// ---------------------------------------------------------------------------
// Kernel 2: per-tile cull -> rank sort (2 barriers) -> composite (chunked)
// ---------------------------------------------------------------------------
__global__ void __launch_bounds__(256) render_kernel(float* __restrict__ out,
                                                     int H, int W, int N)
{
    __shared__ ull    skey[NMAX];     // 8KB  — compacted survivor keys
    __shared__ float4 f0[SMAX];       // 4KB  — staged params, sorted order
    __shared__ float4 f1[SMAX];       // 4KB
    __shared__ float  fcb[SMAX];      // 1KB
    __shared__ int    s_w[9];

    int tid = threadIdx.x;
    int lane = tid & 31;
    int wid = tid >> 5;
    int tx = tid & 15;
    int ty = tid >> 4;
    int pxi = blockIdx.x * 16 + tx;
    int pyi = blockIdx.y * 16 + ty;

    float invW = 1.f / (float)W;
    float pxc = ((float)pxi + 0.5f - 0.5f * (float)W) * invW;
    float pyc = ((float)pyi + 0.5f - 0.5f * (float)H) * invW;
    float xmin = ((float)(blockIdx.x * 16)      + 0.5f - 0.5f * (float)W) * invW;
    float xmax = ((float)(blockIdx.x * 16 + 15) + 0.5f - 0.5f * (float)W) * invW;
    float ymin = ((float)(blockIdx.y * 16)      + 0.5f - 0.5f * (float)H) * invW;
    float ymax = ((float)(blockIdx.y * 16 + 15) + 0.5f - 0.5f * (float)H) * invW;

    // ---- cull: 4 contiguous gaussians per thread ----
    ull lk[4];
    int li[4];
    int cnt = 0;
#pragma unroll
    for (int r = 0; r < 4; r++) {
        int i = tid * 4 + r;
        if (i < N) {
            float4 c = g_cull[i];
            float ddx = fmaxf(fmaxf(xmin - c.x, c.x - xmax), 0.f);
            float ddy = fmaxf(fmaxf(ymin - c.y, c.y - ymax), 0.f);
            if (ddx * ddx + ddy * ddy <= c.z) {
                lk[cnt] = ((ull)__float_as_uint(c.w) << 32) | (unsigned)i;
                li[cnt] = i;
                cnt++;
            }
        }
    }

    // ---- block exclusive scan of per-thread survivor counts ----
    int incl = cnt;
#pragma unroll
    for (int d = 1; d < 32; d <<= 1) {
        int v = __shfl_up_sync(0xFFFFFFFFu, incl, d);
        if (lane >= d) incl += v;
    }
    if (lane == 31) s_w[wid] = incl;
    __syncthreads();
    if (tid == 0) {
        int s = 0;
#pragma unroll
        for (int w = 0; w < 8; w++) { int v = s_w[w]; s_w[w] = s; s += v; }
        s_w[8] = s;
    }
    __syncthreads();
    int base = s_w[wid] + incl - cnt;
    int total = s_w[8];

    for (int j = 0; j < cnt; j++) skey[base + j] = lk[j];
    __syncthreads();

    // ---- rank each of this thread's survivors (keys unique -> permutation)
    int rk[4];
    for (int j = 0; j < cnt; j++) {
        ull mine = lk[j];
        int r = 0;
        for (int k = 0; k < total; k++) r += (skey[k] < mine);
        rk[j] = r;
    }

    // ---- chunked staged composite, front-to-back ----
    float T = 1.f, ar = 0.f, ag = 0.f, ab = 0.f;
    for (int cbase = 0; cbase < total; cbase += SMAX) {
        int cn = min(SMAX, total - cbase);
        // scatter params for ranks in this window, directly into sorted slots
        for (int j = 0; j < cnt; j++) {
            int r = rk[j] - cbase;
            if ((unsigned)r < (unsigned)SMAX) {
                int idx = li[j];
                f0[r]  = g_p0[idx];
                f1[r]  = g_p1[idx];
                fcb[r] = g_cb[idx];
            }
        }
        __syncthreads();

        if (T > TTHR) {
            int Me = cn & ~1;
            int k = 0;
            for (; k < Me; k += 2) {
                float4 p0a = f0[k],     p1a = f1[k];
                float4 p0b = f0[k + 1], p1b = f1[k + 1];
                float cba = fcb[k], cbb = fcb[k + 1];
                float dxa = pxc - p0a.x, dya = pyc - p0a.y;
                float dxb = pxc - p0b.x, dyb = pyc - p0b.y;
                float ea = fmaf(p0a.z * dxa, dxa, fmaf(p0a.w * dxa, dya, p1a.x * dya * dya)) + p1a.y;
                float eb = fmaf(p0b.z * dxb, dxb, fmaf(p0b.w * dxb, dyb, p1b.x * dyb * dyb)) + p1b.y;
                float wa, wb;
                asm("ex2.approx.ftz.f32 %0, %1;" : "=f"(wa) : "f"(ea));
                asm("ex2.approx.ftz.f32 %0, %1;" : "=f"(wb) : "f"(eb));
                float wTa = wa * T;
                ar = fmaf(wTa, p1a.z, ar);
                ag = fmaf(wTa, p1a.w, ag);
                ab = fmaf(wTa, cba, ab);
                float T1 = T * (1.f - fminf(wa, 0.9999f));
                if (T1 > TTHR) {
                    float wTb = wb * T1;
                    ar = fmaf(wTb, p1b.z, ar);
                    ag = fmaf(wTb, p1b.w, ag);
                    ab = fmaf(wTb, cbb, ab);
                    T = T1 * (1.f - fminf(wb, 0.9999f));
                    if (T <= TTHR) break;
                } else {
                    T = T1;
                    break;
                }
            }
            if (k == Me && Me < cn && T > TTHR) {   // odd tail
                float4 p0a = f0[Me], p1a = f1[Me];
                float cba = fcb[Me];
                float dxa = pxc - p0a.x, dya = pyc - p0a.y;
                float ea = fmaf(p0a.z * dxa, dxa, fmaf(p0a.w * dxa, dya, p1a.x * dya * dya)) + p1a.y;
                float wa;
                asm("ex2.approx.ftz.f32 %0, %1;" : "=f"(wa) : "f"(ea));
                float wTa = wa * T;
                ar = fmaf(wTa, p1a.z, ar);
                ag = fmaf(wTa, p1a.w, ag);
                ab = fmaf(wTa, cba, ab);
                T = T * (1.f - fminf(wa, 0.9999f));
            }
        }
        // uniform early exit + protects smem reuse across chunks
        if (__syncthreads_and(T <= TTHR)) break;
    }

    if (pxi < W && pyi < H) {
        int o = (pyi * W + pxi) * 3;
        out[o + 0] = ar;
        out[o + 1] = ag;
        out[o + 2] = ab;
    }
}

// ---------------------------------------------------------------------------
extern "C" void kernel_launch(void* const* d_in, const int* in_sizes, int n_in,
                              void* d_out, int out_size)
{
    const float* mean  = (const float*)d_in[0];
    const float* qvec  = (const float*)d_in[1];
    const float* svecb = (const float*)d_in[2];
    const float* sh    = (const float*)d_in[3];
    const float* alphb = (const float*)d_in[4];
    const float* c2w   = (const float*)d_in[5];

    int N = in_sizes[0] / 3;
    if (N > NMAX) N = NMAX;
    int HW = out_size / 3;
    int W = (int)(sqrtf((float)HW) + 0.5f);
    int H = HW / W;

    precompute_kernel<<<(N + 255) / 256, 256>>>(mean, qvec, svecb, sh, alphb, c2w, N);
    dim3 grid((W + 15) / 16, (H + 15) / 16);
    render_kernel<<<grid, 256>>>((float*)d_out, H, W, N);
}